// round 2
// baseline (speedup 1.0000x reference)
#include <cuda_runtime.h>
#include <cuda_bf16.h>

// CINLayer: out_mat[b,c,d] = sum_{i,j} x[b,i,d] * y[b,j,d] * K[c,i,j]
//           out_fin[b,c]   = sum_d out_mat[b,c,d]
// B=4096, H1=H2=32, D=32, C=64
//
// Thread mapping: warp = one b, lane = d. x[b,:,lane], y[b,:,lane] in registers.
// K is warp-uniform -> broadcast LDS from a staged SMEM chunk.

#define BB 4096
#define HH 32
#define DD 32
#define CC 64
#define C_CHUNK 8
#define WARPS_PER_BLOCK 8

__global__ __launch_bounds__(WARPS_PER_BLOCK * 32, 2)
void cin_kernel(const float* __restrict__ x,
                const float* __restrict__ y,
                const float* __restrict__ K,
                float* __restrict__ out_mat,
                float* __restrict__ out_fin) {
    __shared__ float Ks[C_CHUNK * HH * HH];   // 8 * 1024 floats = 32 KB

    const int lane = threadIdx.x & 31;
    const int warp = threadIdx.x >> 5;
    const int b = blockIdx.x * WARPS_PER_BLOCK + warp;
    const int d = lane;

    // Load x[b,:,d] and y[b,:,d] into registers (coalesced: 128B per i).
    float xr[HH], yr[HH];
    const float* xb = x + (size_t)b * HH * DD + d;
    const float* yb = y + (size_t)b * HH * DD + d;
#pragma unroll
    for (int i = 0; i < HH; i++) {
        xr[i] = xb[i * DD];
        yr[i] = yb[i * DD];
    }

    for (int cc = 0; cc < CC; cc += C_CHUNK) {
        __syncthreads();
        // Stage K[cc : cc+C_CHUNK] into SMEM: 2048 float4 across 256 threads.
        {
            const float4* Kg = (const float4*)(K + cc * HH * HH);
            float4* Ksv = (float4*)Ks;
#pragma unroll
            for (int t = 0; t < (C_CHUNK * HH * HH / 4) / (WARPS_PER_BLOCK * 32); t++)
                Ksv[threadIdx.x + t * (WARPS_PER_BLOCK * 32)] =
                    Kg[threadIdx.x + t * (WARPS_PER_BLOCK * 32)];
        }
        __syncthreads();

        for (int c = 0; c < C_CHUNK; c++) {
            const float* Kc = Ks + c * HH * HH;
            float acc = 0.0f;
#pragma unroll
            for (int i = 0; i < HH; i++) {
                const float4* Kr = (const float4*)(Kc + i * HH);
                float s0 = 0.f, s1 = 0.f, s2 = 0.f, s3 = 0.f;
#pragma unroll
                for (int j4 = 0; j4 < HH / 4; j4++) {
                    float4 k = Kr[j4];           // warp-uniform broadcast LDS.128
                    s0 = fmaf(k.x, yr[4 * j4 + 0], s0);
                    s1 = fmaf(k.y, yr[4 * j4 + 1], s1);
                    s2 = fmaf(k.z, yr[4 * j4 + 2], s2);
                    s3 = fmaf(k.w, yr[4 * j4 + 3], s3);
                }
                acc = fmaf(xr[i], (s0 + s1) + (s2 + s3), acc);
            }
            // output_mat[b, cc+c, d]  (coalesced across lanes)
            out_mat[((size_t)b * CC + cc + c) * DD + d] = acc;

            // final_output[b, cc+c] = sum over d (lanes)
            float f = acc;
#pragma unroll
            for (int o = 16; o > 0; o >>= 1)
                f += __shfl_xor_sync(0xFFFFFFFFu, f, o);
            if (lane == 0)
                out_fin[(size_t)b * CC + cc + c] = f;
        }
    }
}

extern "C" void kernel_launch(void* const* d_in, const int* in_sizes, int n_in,
                              void* d_out, int out_size) {
    const float* x = (const float*)d_in[0];   // [B, H1, D]
    const float* y = (const float*)d_in[1];   // [B, H2, D]
    const float* K = (const float*)d_in[2];   // [C, H1, H2]

    float* out_mat = (float*)d_out;                                // [B, C, D]
    float* out_fin = (float*)d_out + (size_t)BB * CC * DD;         // [B, C]

    dim3 grid(BB / WARPS_PER_BLOCK);
    dim3 block(WARPS_PER_BLOCK * 32);
    cin_kernel<<<grid, block>>>(x, y, K, out_mat, out_fin);
}

// round 3
// speedup vs baseline: 5.6619x; 5.6619x over previous
#include <cuda_runtime.h>
#include <cuda_fp16.h>
#include <stdint.h>

// CINLayer on tensor cores:
//   out_mat[b,c,d] = sum_ij K2[c,ij] * z_b[ij,d],  z_b[ij,d] = x[b,i,d]*y[b,j,d]
//   out_fin[b,c]   = sum_d out_mat[b,c,d]
// Per b: GEMM M=64 (c), N=32 (d), K=1024 (ij) via mma.sync.m16n8k16 fp16->fp32.

#define BB 4096
#define IJ 1024
#define CC 64
#define DD 32
#define KROW 2064                    // padded f16 row stride for K2 (bytes): conflict-free ldmatrix
#define NT 256

#define OFF_K2  0
#define OFF_Z   (CC * KROW)          // 132096
#define OFF_XH  (OFF_Z + IJ * 64)    // 197632
#define OFF_YH  (OFF_XH + 2048)      // 199680
#define OFF_FIN (OFF_YH + 2048)      // 201728
#define SMEM_BYTES (OFF_FIN + 256)   // 201984

__device__ __forceinline__ unsigned hm2(unsigned a, unsigned b) {
    __half2 r = __hmul2(*(__half2*)&a, *(__half2*)&b);
    return *(unsigned*)&r;
}

__device__ __forceinline__ void ldmat4(unsigned& r0, unsigned& r1, unsigned& r2, unsigned& r3,
                                       uint32_t addr) {
    asm volatile("ldmatrix.sync.aligned.m8n8.x4.shared.b16 {%0,%1,%2,%3}, [%4];"
                 : "=r"(r0), "=r"(r1), "=r"(r2), "=r"(r3) : "r"(addr));
}
__device__ __forceinline__ void ldmat4t(unsigned& r0, unsigned& r1, unsigned& r2, unsigned& r3,
                                        uint32_t addr) {
    asm volatile("ldmatrix.sync.aligned.m8n8.x4.trans.shared.b16 {%0,%1,%2,%3}, [%4];"
                 : "=r"(r0), "=r"(r1), "=r"(r2), "=r"(r3) : "r"(addr));
}
__device__ __forceinline__ void mma16816(float& c0, float& c1, float& c2, float& c3,
                                         unsigned a0, unsigned a1, unsigned a2, unsigned a3,
                                         unsigned b0, unsigned b1) {
    asm volatile("mma.sync.aligned.m16n8k16.row.col.f32.f16.f16.f32 "
                 "{%0,%1,%2,%3}, {%4,%5,%6,%7}, {%8,%9}, {%0,%1,%2,%3};"
                 : "+f"(c0), "+f"(c1), "+f"(c2), "+f"(c3)
                 : "r"(a0), "r"(a1), "r"(a2), "r"(a3), "r"(b0), "r"(b1));
}

__global__ __launch_bounds__(NT, 1)
void cin_mma_kernel(const float* __restrict__ x, const float* __restrict__ y,
                    const float* __restrict__ K, float* __restrict__ out_mat,
                    float* __restrict__ out_fin) {
    extern __shared__ char smem[];
    __half* K2s = (__half*)(smem + OFF_K2);
    char*   zb  = smem + OFF_Z;
    __half* xh  = (__half*)(smem + OFF_XH);
    __half* yh  = (__half*)(smem + OFF_YH);
    float*  finb = (float*)(smem + OFF_FIN);

    const int tid  = threadIdx.x;
    const int lane = tid & 31;
    const int w    = tid >> 5;
    const int mt   = w >> 1;   // 0..3 : c-tile (16 rows)
    const int nt   = w & 1;    // 0..1 : d-tile (16 cols)

    const uint32_t smem_u32 = (uint32_t)__cvta_generic_to_shared(smem);

    // ---- stage K once: f32 [64][1024] -> f16 rows padded to KROW bytes
    for (int p = tid; p < CC * IJ / 2; p += NT) {
        int row = p >> 9;            // (2p)/1024
        int col = (2 * p) & (IJ - 1);
        float2 v = *(const float2*)(K + 2 * p);
        *(__half2*)((char*)K2s + row * KROW + col * 2) = __floats2half2_rn(v.x, v.y);
    }

    // ldmatrix lane addresses (constant per lane across the k-loop)
    const int lrow = lane & 15;
    const uint32_t a_base = smem_u32 + OFF_K2 + (mt * 16 + lrow) * KROW + (lane >> 4) * 16;
    const int bchunk = (nt * 2 + (lane >> 4)) ^ ((lrow >> 1) & 3);   // XOR swizzle
    const uint32_t b_base = smem_u32 + OFF_Z + lrow * 64 + bchunk * 16;

    for (int b = blockIdx.x; b < BB; b += gridDim.x) {
        // ---- stage x[b], y[b] -> f16 smem (1024 floats each; one float4 per thread)
        {
            float4 vx = ((const float4*)(x + (size_t)b * IJ))[tid];
            float4 vy = ((const float4*)(y + (size_t)b * IJ))[tid];
            *(__half2*)(xh + tid * 4)     = __floats2half2_rn(vx.x, vx.y);
            *(__half2*)(xh + tid * 4 + 2) = __floats2half2_rn(vx.z, vx.w);
            *(__half2*)(yh + tid * 4)     = __floats2half2_rn(vy.x, vy.y);
            *(__half2*)(yh + tid * 4 + 2) = __floats2half2_rn(vy.z, vy.w);
        }
        __syncthreads();

        // ---- z-gen: warp w covers i in [4w, 4w+4); lane = j; rows swizzled
        {
            const int j = lane;
            const int swz = (j >> 1) & 3;
            const uint4* yrow = (const uint4*)(yh + j * 32);
            uint4 y0 = yrow[0], y1 = yrow[1], y2 = yrow[2], y3 = yrow[3];
            char* zrowj = zb + j * 64;
#pragma unroll
            for (int ii = 0; ii < 4; ii++) {
                const int i = w * 4 + ii;
                const uint4* xrow = (const uint4*)(xh + i * 32);  // broadcast LDS
                uint4 x0 = xrow[0], x1 = xrow[1], x2 = xrow[2], x3 = xrow[3];
                char* zr = zrowj + i * 2048;
                uint4 z;
                z.x = hm2(x0.x, y0.x); z.y = hm2(x0.y, y0.y);
                z.z = hm2(x0.z, y0.z); z.w = hm2(x0.w, y0.w);
                *(uint4*)(zr + ((0 ^ swz) * 16)) = z;
                z.x = hm2(x1.x, y1.x); z.y = hm2(x1.y, y1.y);
                z.z = hm2(x1.z, y1.z); z.w = hm2(x1.w, y1.w);
                *(uint4*)(zr + ((1 ^ swz) * 16)) = z;
                z.x = hm2(x2.x, y2.x); z.y = hm2(x2.y, y2.y);
                z.z = hm2(x2.z, y2.z); z.w = hm2(x2.w, y2.w);
                *(uint4*)(zr + ((2 ^ swz) * 16)) = z;
                z.x = hm2(x3.x, y3.x); z.y = hm2(x3.y, y3.y);
                z.z = hm2(x3.z, y3.z); z.w = hm2(x3.w, y3.w);
                *(uint4*)(zr + ((3 ^ swz) * 16)) = z;
            }
        }
        __syncthreads();

        // ---- MMA: warp tile 16x16 of the 64x32 output, K=1024
        float c00 = 0.f, c01 = 0.f, c02 = 0.f, c03 = 0.f;   // n-cols 0-7 of tile
        float c10 = 0.f, c11 = 0.f, c12 = 0.f, c13 = 0.f;   // n-cols 8-15
        {
            uint32_t aaddr = a_base, baddr = b_base;
#pragma unroll 8
            for (int ks = 0; ks < IJ / 16; ks++) {
                unsigned a0, a1, a2, a3, b0, b1, b2, b3;
                ldmat4(a0, a1, a2, a3, aaddr);
                ldmat4t(b0, b1, b2, b3, baddr);
                mma16816(c00, c01, c02, c03, a0, a1, a2, a3, b0, b1);
                mma16816(c10, c11, c12, c13, a0, a1, a2, a3, b2, b3);
                aaddr += 32;     // 16 halves along padded K2 row
                baddr += 1024;   // 16 z rows * 64 B
            }
        }

        // ---- epilogue
        {
            const int r0 = lane >> 2, q = lane & 3;
            const int cg0 = mt * 16 + r0, cg1 = cg0 + 8;
            const int d0 = nt * 16 + q * 2;
            float* om = out_mat + ((size_t)b * CC) * DD;
            float2 s;
            s.x = c00; s.y = c01; *(float2*)(om + cg0 * DD + d0)     = s;
            s.x = c10; s.y = c11; *(float2*)(om + cg0 * DD + d0 + 8) = s;
            s.x = c02; s.y = c03; *(float2*)(om + cg1 * DD + d0)     = s;
            s.x = c12; s.y = c13; *(float2*)(om + cg1 * DD + d0 + 8) = s;

            float p0 = (c00 + c01) + (c10 + c11);
            float p1 = (c02 + c03) + (c12 + c13);
            p0 += __shfl_xor_sync(0xFFFFFFFFu, p0, 1);
            p0 += __shfl_xor_sync(0xFFFFFFFFu, p0, 2);
            p1 += __shfl_xor_sync(0xFFFFFFFFu, p1, 1);
            p1 += __shfl_xor_sync(0xFFFFFFFFu, p1, 2);
            if (q == 0 && nt == 1) { finb[cg0] = p0; finb[cg1] = p1; }
            __syncthreads();   // finb ready; z consumed (safe to overwrite next iter)
            if (q == 0 && nt == 0) {
                out_fin[(size_t)b * CC + cg0] = p0 + finb[cg0];
                out_fin[(size_t)b * CC + cg1] = p1 + finb[cg1];
            }
        }
    }
}

extern "C" void kernel_launch(void* const* d_in, const int* in_sizes, int n_in,
                              void* d_out, int out_size) {
    const float* x = (const float*)d_in[0];   // [B, 32, 32]
    const float* y = (const float*)d_in[1];   // [B, 32, 32]
    const float* K = (const float*)d_in[2];   // [64, 32, 32]

    float* out_mat = (float*)d_out;                          // [B, 64, 32]
    float* out_fin = (float*)d_out + (size_t)BB * CC * DD;   // [B, 64]

    static int smem_set = 0;
    if (!smem_set) {
        cudaFuncSetAttribute(cin_mma_kernel,
                             cudaFuncAttributeMaxDynamicSharedMemorySize, SMEM_BYTES);
        smem_set = 1;
    }
    cin_mma_kernel<<<148, NT, SMEM_BYTES>>>(x, y, K, out_mat, out_fin);
}

// round 8
// speedup vs baseline: 9.4404x; 1.6674x over previous
#include <cuda_runtime.h>
#include <cuda_fp16.h>
#include <stdint.h>

// CINLayer via mma.sync (HMMA), z generated in registers:
//   out_mat[c, (b,d)] = sum_k K2[c,k] * z[k,(b,d)],  z[k=(i,j), d] = x[b,i,d]*y[b,j,d]
// Warp tile m32 x n64 (2 b's share one A pass). 8 warps = 2 c-halves x 4 b-pairs.

#define BB 4096
#define IJ 1024
#define CC 64
#define DD 32
#define KROW 2064                 // padded K2 row stride (bytes), conflict-free ldmatrix
#define NT 256
#define BPG 8                     // b per CTA group
#define NGROUP (BB / BPG)         // 512
#define NCTA 148
#define YTB (17 * 32 * 4)         // 2176 B: yT[d][a] pairs, stride 17 words

#define OFF_K2 0
#define OFF_XD (CC * KROW)              // 132096
#define OFF_YT (OFF_XD + BPG * 4096)    // 164864
#define SMEM_BYTES (OFF_YT + BPG * YTB) // 182272

__device__ __forceinline__ uint32_t smem_u32(const void* p) {
    uint32_t a;
    asm("{ .reg .u64 t; cvta.to.shared.u64 t, %1; cvt.u32.u64 %0, t; }" : "=r"(a) : "l"(p));
    return a;
}
__device__ __forceinline__ unsigned hm2(unsigned a, unsigned b) {
    __half2 r = __hmul2(*(__half2*)&a, *(__half2*)&b);
    return *(unsigned*)&r;
}
__device__ __forceinline__ void ldmat4(unsigned& r0, unsigned& r1, unsigned& r2, unsigned& r3,
                                       uint32_t addr) {
    asm volatile("ldmatrix.sync.aligned.m8n8.x4.shared.b16 {%0,%1,%2,%3}, [%4];"
                 : "=r"(r0), "=r"(r1), "=r"(r2), "=r"(r3) : "r"(addr));
}
__device__ __forceinline__ void mma16816(float& c0, float& c1, float& c2, float& c3,
                                         unsigned a0, unsigned a1, unsigned a2, unsigned a3,
                                         unsigned b0, unsigned b1) {
    asm volatile("mma.sync.aligned.m16n8k16.row.col.f32.f16.f16.f32 "
                 "{%0,%1,%2,%3}, {%4,%5,%6,%7}, {%8,%9}, {%0,%1,%2,%3};"
                 : "+f"(c0), "+f"(c1), "+f"(c2), "+f"(c3)
                 : "r"(a0), "r"(a1), "r"(a2), "r"(a3), "r"(b0), "r"(b1));
}

__global__ __launch_bounds__(NT, 1)
void cin_hmma_kernel(const float* __restrict__ x, const float* __restrict__ y,
                     const float* __restrict__ K, float* __restrict__ out_mat,
                     float* __restrict__ out_fin) {
    extern __shared__ char smem[];
    const int tid = threadIdx.x, lane = tid & 31, wid = tid >> 5;

    // ---- stage K2 once: f32 [64][1024] -> f16 rows padded to KROW bytes (R2-proven)
    for (int p = tid; p < CC * IJ / 2; p += NT) {
        int row = p >> 9;
        int col = (2 * p) & (IJ - 1);
        float2 v = *(const float2*)(K + 2 * p);
        *(__half2*)(smem + OFF_K2 + row * KROW + col * 2) = __floats2half2_rn(v.x, v.y);
    }

    const int mh = wid & 1, pr = wid >> 1;      // c-half, b-pair
    const int q = lane & 3, gid = lane >> 2;
    const uint32_t aA0 = smem_u32(smem) + OFF_K2 +
                         (uint32_t)(mh * 32 + (lane & 15)) * KROW + (lane >> 4) * 16;

    for (int grp = blockIdx.x; grp < NGROUP; grp += gridDim.x) {
        const int base_b = grp * BPG;
        __syncthreads();            // prior compute done before restaging

        // ---- stage 8 b's: xdup[i][d] = half2(x,x); yT[d][a] = half2(y[2a,d],y[2a+1,d])
        {
            const int d = tid & 31, ab = tid >> 5;
#pragma unroll
            for (int lb = 0; lb < BPG; lb++) {
                const float* xb = x + (size_t)(base_b + lb) * IJ;
                const float* yb = y + (size_t)(base_b + lb) * IJ;
                float4 v = ((const float4*)xb)[tid];
                uint4 u;
                { __half2 h = __half2half2(__float2half_rn(v.x)); u.x = *(unsigned*)&h; }
                { __half2 h = __half2half2(__float2half_rn(v.y)); u.y = *(unsigned*)&h; }
                { __half2 h = __half2half2(__float2half_rn(v.z)); u.z = *(unsigned*)&h; }
                { __half2 h = __half2half2(__float2half_rn(v.w)); u.w = *(unsigned*)&h; }
                ((uint4*)(smem + OFF_XD + lb * 4096))[tid] = u;

                unsigned* yT = (unsigned*)(smem + OFF_YT + lb * YTB);
#pragma unroll
                for (int rep = 0; rep < 2; rep++) {
                    int a = ab + 8 * rep;
                    float v0 = yb[(2 * a) * DD + d];
                    float v1 = yb[(2 * a + 1) * DD + d];
                    __half2 h = __floats2half2_rn(v0, v1);
                    yT[d * 17 + a] = *(unsigned*)&h;
                }
            }
        }
        __syncthreads();

        // ---- per-warp: preload y pairs for its 2 b's (4 d-groups x 4 k-phases)
        const int lb0 = 2 * pr;
        unsigned ys[2][4][4];
#pragma unroll
        for (int bb = 0; bb < 2; bb++) {
            const unsigned* yT = (const unsigned*)(smem + OFF_YT + (lb0 + bb) * YTB);
#pragma unroll
            for (int g = 0; g < 4; g++)
#pragma unroll
                for (int s = 0; s < 4; s++)
                    ys[bb][g][s] = yT[(8 * g + gid) * 17 + q + 4 * s];
        }
        const unsigned* xd0 = (const unsigned*)(smem + OFF_XD + lb0 * 4096);
        const unsigned* xd1 = (const unsigned*)(smem + OFF_XD + (lb0 + 1) * 4096);

        float acc[2][8][4];
#pragma unroll
        for (int m = 0; m < 2; m++)
#pragma unroll
            for (int n = 0; n < 8; n++)
#pragma unroll
                for (int e = 0; e < 4; e++) acc[m][n][e] = 0.f;

        unsigned xd[2][4];
#pragma unroll 4
        for (int t = 0; t < 64; t++) {
            if (!(t & 1)) {
                const int i = t >> 1;
#pragma unroll
                for (int g = 0; g < 4; g++) {
                    xd[0][g] = xd0[i * 32 + 8 * g + gid];
                    xd[1][g] = xd1[i * 32 + 8 * g + gid];
                }
            }
            unsigned A0[4], A1[4];
            ldmat4(A0[0], A0[1], A0[2], A0[3], aA0 + t * 32);
            ldmat4(A1[0], A1[1], A1[2], A1[3], aA0 + 16 * KROW + t * 32);
            const int s0 = 2 * (t & 1);
#pragma unroll
            for (int bb = 0; bb < 2; bb++)
#pragma unroll
                for (int g = 0; g < 4; g++) {
                    unsigned bf0 = hm2(xd[bb][g], ys[bb][g][s0]);
                    unsigned bf1 = hm2(xd[bb][g], ys[bb][g][s0 + 1]);
                    const int n8 = bb * 4 + g;
                    mma16816(acc[0][n8][0], acc[0][n8][1], acc[0][n8][2], acc[0][n8][3],
                             A0[0], A0[1], A0[2], A0[3], bf0, bf1);
                    mma16816(acc[1][n8][0], acc[1][n8][1], acc[1][n8][2], acc[1][n8][3],
                             A1[0], A1[1], A1[2], A1[3], bf0, bf1);
                }
        }

        // ---- epilogue: out_mat + d-reduced out_fin
#pragma unroll
        for (int bb = 0; bb < 2; bb++) {
            const int b = base_b + lb0 + bb;
            float* om = out_mat + (size_t)b * CC * DD;
#pragma unroll
            for (int m = 0; m < 2; m++) {
                const int c0 = mh * 32 + m * 16 + gid;
                float slo = 0.f, shi = 0.f;
#pragma unroll
                for (int g = 0; g < 4; g++) {
                    const int n8 = bb * 4 + g;
                    const int d0 = 8 * g + 2 * q;
                    *(float2*)(om + c0 * DD + d0) =
                        make_float2(acc[m][n8][0], acc[m][n8][1]);
                    *(float2*)(om + (c0 + 8) * DD + d0) =
                        make_float2(acc[m][n8][2], acc[m][n8][3]);
                    slo += acc[m][n8][0] + acc[m][n8][1];
                    shi += acc[m][n8][2] + acc[m][n8][3];
                }
                slo += __shfl_xor_sync(0xFFFFFFFFu, slo, 1);
                slo += __shfl_xor_sync(0xFFFFFFFFu, slo, 2);
                shi += __shfl_xor_sync(0xFFFFFFFFu, shi, 1);
                shi += __shfl_xor_sync(0xFFFFFFFFu, shi, 2);
                if (q == 0) {
                    out_fin[(size_t)b * CC + c0] = slo;
                    out_fin[(size_t)b * CC + c0 + 8] = shi;
                }
            }
        }
    }
}

extern "C" void kernel_launch(void* const* d_in, const int* in_sizes, int n_in,
                              void* d_out, int out_size) {
    const float* x = (const float*)d_in[0];   // [B, 32, 32]
    const float* y = (const float*)d_in[1];   // [B, 32, 32]
    const float* K = (const float*)d_in[2];   // [64, 32, 32]
    float* out_mat = (float*)d_out;                          // [B, 64, 32]
    float* out_fin = (float*)d_out + (size_t)BB * CC * DD;   // [B, 64]

    static int done = 0;
    if (!done) {
        cudaFuncSetAttribute(cin_hmma_kernel,
                             cudaFuncAttributeMaxDynamicSharedMemorySize, SMEM_BYTES);
        done = 1;
    }
    cin_hmma_kernel<<<NCTA, NT, SMEM_BYTES>>>(x, y, K, out_mat, out_fin);
}